// round 1
// baseline (speedup 1.0000x reference)
#include <cuda_runtime.h>

#define T_DIM 4096
#define D_DIM 64
#define B_DIM 32

// Per-thread pyramid transition for level size M (coarse length M, fine length 2M).
// Covers windows W = M (exact, d = coarse array) and W = M+1 .. 2M-1 (mixed).
// Fine-prefix contributions are re-associated through suffix-summed duration
// weights so no prefix array is materialized.
template<int M>
__device__ __forceinline__ void transition(const float* __restrict__ F,
                                           float* __restrict__ C,
                                           const float* __restrict__ pmv,
                                           const float* __restrict__ dmb,
                                           int low, int up, float& res)
{
    float ft[M];
#pragma unroll
    for (int j = 0; j < M; j++) {
        float a = F[2 * j], b = F[2 * j + 1];
        C[j]  = 0.5f * (a + b);
        ft[j] = fmaf(a, pmv[2 * j], b * pmv[2 * j + 1]);
    }
    float suf = 0.f;
#pragma unroll
    for (int p = M - 1; p >= 1; p--) {
        const int W = M + p;
        float w = 0.f;
        if (W >= low && W < up) w = dmb[(W - 1) * T_DIM];
        float sc = 0.f;
#pragma unroll
        for (int j = p; j < M; j++) sc = fmaf(C[j], pmv[j + p], sc);
        res = fmaf(w, sc, res);
        suf += w;
        res = fmaf(ft[p - 1], suf, res);
    }
    {   // p = 0: exact window W = M, d = coarse array
        float w = 0.f;
        if (M >= low && M < up) w = dmb[(M - 1) * T_DIM];
        float sc = 0.f;
#pragma unroll
        for (int j = 0; j < M; j++) sc = fmaf(C[j], pmv[j], sc);
        res = fmaf(w, sc, res);
    }
}

// First transition (M=32): fine level is rep itself, streamed straight from
// GMEM so the 64-element level-0 array never occupies registers.
__device__ __forceinline__ void transition32_load(const float* __restrict__ repb,
                                                  float* __restrict__ C,
                                                  const float* __restrict__ pmv,
                                                  const float* __restrict__ dmb,
                                                  int low, int up, float& res)
{
    constexpr int M = 32;
    float ft[M];
#pragma unroll
    for (int j = 0; j < M; j++) {
        float a = repb[(2 * j) * T_DIM];
        float b = repb[(2 * j + 1) * T_DIM];
        C[j]  = 0.5f * (a + b);
        ft[j] = fmaf(a, pmv[2 * j], b * pmv[2 * j + 1]);
    }
    float suf = 0.f;
#pragma unroll
    for (int p = M - 1; p >= 1; p--) {
        const int W = M + p;
        float w = 0.f;
        if (W >= low && W < up) w = dmb[(W - 1) * T_DIM];
        float sc = 0.f;
#pragma unroll
        for (int j = p; j < M; j++) sc = fmaf(C[j], pmv[j + p], sc);
        res = fmaf(w, sc, res);
        suf += w;
        res = fmaf(ft[p - 1], suf, res);
    }
    {
        float w = 0.f;
        if (M >= low && M < up) w = dmb[(M - 1) * T_DIM];
        float sc = 0.f;
#pragma unroll
        for (int j = 0; j < M; j++) sc = fmaf(C[j], pmv[j], sc);
        res = fmaf(w, sc, res);
    }
}

__global__ __launch_bounds__(256)
void ContextGenerator_34875134444049_kernel(const float* __restrict__ rep,
                                            const float* __restrict__ dmask,
                                            const float* __restrict__ pmask,
                                            const int* __restrict__ lowp,
                                            const int* __restrict__ upp,
                                            float* __restrict__ out)
{
    const int gid = blockIdx.x * 256 + threadIdx.x;   // 0 .. B*T-1
    const int b = gid >> 12;                          // T = 4096
    const int t = gid & (T_DIM - 1);
    const int base = b * (D_DIM * T_DIM) + t;

    const int low = *lowp;
    const int up  = *upp;

    const float* __restrict__ pmb = pmask + base;
    const float* __restrict__ dmb = dmask + base;

    float pmv[64];
#pragma unroll
    for (int w = 0; w < 64; w++) pmv[w] = pmb[w * T_DIM];

    float res = 0.f;

    float L1[32]; transition32_load(rep + base, L1, pmv, dmb, low, up, res);
    float L2[16]; transition<16>(L1, L2, pmv, dmb, low, up, res);
    float L3[8];  transition<8>(L2, L3, pmv, dmb, low, up, res);
    float L4[4];  transition<4>(L3, L4, pmv, dmb, low, up, res);
    float L5[2];  transition<2>(L4, L5, pmv, dmb, low, up, res);

    // W = 1: d = deepest level (single element)
    const float x6 = 0.5f * (L5[0] + L5[1]);
    if (1 >= low && 1 < up) res = fmaf(dmb[0], x6 * pmv[0], res);

    out[gid] = res;   // [B, 1, T] flat = gid
}

extern "C" void kernel_launch(void* const* d_in, const int* in_sizes, int n_in,
                              void* d_out, int out_size)
{
    const float* rep   = (const float*)d_in[0];
    const float* dmask = (const float*)d_in[1];
    const float* pmask = (const float*)d_in[2];
    const int*   lowp  = (const int*)d_in[3];
    const int*   upp   = (const int*)d_in[4];
    float* out = (float*)d_out;

    const int total = B_DIM * T_DIM;           // 131072
    ContextGenerator_34875134444049_kernel<<<total / 256, 256>>>(
        rep, dmask, pmask, lowp, upp, out);
}